// round 11
// baseline (speedup 1.0000x reference)
#include <cuda_runtime.h>

// TSM temporal shift: x shape (bt=128, c=96, h=56, w=56), N_FRAME=8, fold=32.
// out[b,t, 0:32] = x[b,t+1, 0:32]  (zero at t=7)
// out[b,t,32:64] = x[b,t-1,32:64]  (zero at t=0)
// out[b,t,64:96] = x[b,t,  64:96]
//
// R9: region-chunk decomposition. The shift is UNIFORM across each 32-channel
// group, so the whole op is 384 contiguous 1.6MB chunk copies (or zero fills)
// with one uniform source delta each. 16 CTAs per chunk, each copying 1568
// contiguous float4 (2 planes) with 6 front-batched LDG.128.CS + 1 tail warp.
// Branchless warp-uniform addressing; MLP x occupancy stays at saturation.

#define C_DIM      96
#define N_FRAME    8
#define FOLD       32
#define HW4        784            // 56*56/4
#define CHUNK_F4   25088          // 32 planes * 784
#define CTA_F4     1568           // CHUNK_F4 / 16  (2 planes)
#define DELTA      ((long)C_DIM * HW4)   // 96 planes in float4 units

__global__ __launch_bounds__(256, 6) void tsm_shift_kernel(
    const float4* __restrict__ x, float4* __restrict__ out)
{
    const int bid   = blockIdx.x;          // 0..6143
    const int chunk = bid >> 4;            // 0..383  = bt*3 + g
    const int sub   = bid & 15;
    const int g     = chunk % 3;           // channel group
    const int bt    = chunk / 3;
    const int t     = bt & (N_FRAME - 1);

    // Uniform per-chunk source delta / zero flag.
    long delta = 0;
    bool zero = false;
    if (g == 0)      { if (t < N_FRAME - 1) delta =  DELTA; else zero = true; }
    else if (g == 1) { if (t > 0)           delta = -DELTA; else zero = true; }

    const long base = (long)chunk * CHUNK_F4 + (long)sub * CTA_F4;
    float4* dst = out + base;
    const float4* src = x + base + delta;

    const int tid = threadIdx.x;
    const bool tail = (tid < CTA_F4 - 6 * 256);    // tid < 32 (one warp)

    if (!zero) {
        // Front-batch 6 (+1 tail) independent LDG.128.CS, then store.
        float4 v0 = __ldcs(src + tid);
        float4 v1 = __ldcs(src + tid +  256);
        float4 v2 = __ldcs(src + tid +  512);
        float4 v3 = __ldcs(src + tid +  768);
        float4 v4 = __ldcs(src + tid + 1024);
        float4 v5 = __ldcs(src + tid + 1280);
        float4 v6;
        if (tail) v6 = __ldcs(src + tid + 1536);
        __stcs(dst + tid,        v0);
        __stcs(dst + tid +  256, v1);
        __stcs(dst + tid +  512, v2);
        __stcs(dst + tid +  768, v3);
        __stcs(dst + tid + 1024, v4);
        __stcs(dst + tid + 1280, v5);
        if (tail) __stcs(dst + tid + 1536, v6);
    } else {
        const float4 z = make_float4(0.f, 0.f, 0.f, 0.f);
        __stcs(dst + tid,        z);
        __stcs(dst + tid +  256, z);
        __stcs(dst + tid +  512, z);
        __stcs(dst + tid +  768, z);
        __stcs(dst + tid + 1024, z);
        __stcs(dst + tid + 1280, z);
        if (tail) __stcs(dst + tid + 1536, z);
    }
}

extern "C" void kernel_launch(void* const* d_in, const int* in_sizes, int n_in,
                              void* d_out, int out_size)
{
    const float4* x = (const float4*)d_in[0];
    float4* out = (float4*)d_out;
    tsm_shift_kernel<<<6144, 256>>>(x, out);   // 384 chunks * 16 CTAs
}